// round 12
// baseline (speedup 1.0000x reference)
#include <cuda_runtime.h>
#include <cuda_fp16.h>
#include <math.h>
#include <stdint.h>

#define T_SEQ 2048
#define BATCH 2
#define DMODEL 2048
#define HQ 16
#define HKV 4
#define HD 128
#define M_ROWS (BATCH*T_SEQ)   /* 4096 */
#define DKV (HKV*HD)           /* 512 */
#define FA_SCALE 0.08838834764831845f
#define LOG2E 1.4426950408889634f

// ---------------- scratch ---------------------------------------------------
__device__ __half g_xh[M_ROWS*DMODEL];
__device__ __half g_Wqh[DMODEL*DMODEL];
__device__ __half g_Wkh[DMODEL*DKV];
__device__ __half g_Wvh[DMODEL*DKV];
__device__ __half g_Woh[DMODEL*DMODEL];
__device__ __half g_Qh[M_ROWS*DMODEL];
__device__ __half g_Kh[M_ROWS*DKV];
__device__ __half g_Vh[M_ROWS*DKV];
__device__ __half g_AOh[M_ROWS*DMODEL];
__device__ float  g_cos[T_SEQ*64];
__device__ float  g_sin[T_SEQ*64];

// ---------------- helpers ----------------------------------------------------
__device__ __forceinline__ uint32_t f2h2(float a, float b) {
    __half2 h = __halves2half2(__float2half_rn(a), __float2half_rn(b));
    return *reinterpret_cast<uint32_t*>(&h);
}
__device__ __forceinline__ uint32_t cvta_smem(const void* p) {
    uint32_t a;
    asm("{ .reg .u64 t; cvta.to.shared.u64 t, %1; cvt.u32.u64 %0, t; }"
        : "=r"(a) : "l"(p));
    return a;
}
__device__ __forceinline__ void mma16(float* d, const uint32_t* a, const uint32_t* b) {
    asm volatile("mma.sync.aligned.m16n8k16.row.col.f32.f16.f16.f32 "
        "{%0,%1,%2,%3}, {%4,%5,%6,%7}, {%8,%9}, {%0,%1,%2,%3};"
        : "+f"(d[0]), "+f"(d[1]), "+f"(d[2]), "+f"(d[3])
        : "r"(a[0]), "r"(a[1]), "r"(a[2]), "r"(a[3]), "r"(b[0]), "r"(b[1]));
}
__device__ __forceinline__ void ldsm4(uint32_t* r, uint32_t a) {
    asm volatile("ldmatrix.sync.aligned.m8n8.x4.shared.b16 {%0,%1,%2,%3}, [%4];"
        : "=r"(r[0]), "=r"(r[1]), "=r"(r[2]), "=r"(r[3]) : "r"(a));
}
__device__ __forceinline__ void ldsm4t(uint32_t* r, uint32_t a) {
    asm volatile("ldmatrix.sync.aligned.m8n8.x4.trans.shared.b16 {%0,%1,%2,%3}, [%4];"
        : "=r"(r[0]), "=r"(r[1]), "=r"(r[2]), "=r"(r[3]) : "r"(a));
}
__device__ __forceinline__ void cp16(uint32_t dst, const void* src) {
    asm volatile("cp.async.cg.shared.global [%0], [%1], 16;" :: "r"(dst), "l"(src));
}
#define CPCOMMIT() asm volatile("cp.async.commit_group;" ::: "memory")
#define CPWAIT1()  asm volatile("cp.async.wait_group 1;" ::: "memory")
#define CPWAIT0()  asm volatile("cp.async.wait_group 0;" ::: "memory")

// ---------------- input conversion fp32 -> fp16 (4 float4 per thread) -------
#define N_X  ((long)M_ROWS*DMODEL/4)
#define N_WQ ((long)DMODEL*DMODEL/4)
#define N_WK ((long)DMODEL*DKV/4)
#define CONV_TOTAL (N_X + 2*N_WQ + 2*N_WK)

__global__ void conv_all(const float* __restrict__ x, const float* __restrict__ wq,
                         const float* __restrict__ wk, const float* __restrict__ wv,
                         const float* __restrict__ wo) {
    long base = (long)blockIdx.x*1024 + threadIdx.x;
    #pragma unroll
    for (int u = 0; u < 4; u++) {
        long i = base + u*256;
        const float* src; __half* dst; long off;
        if (i < N_X)                       { src = x;  dst = g_xh;  off = i; }
        else if (i < N_X + N_WQ)           { src = wq; dst = g_Wqh; off = i - N_X; }
        else if (i < N_X + N_WQ + N_WK)    { src = wk; dst = g_Wkh; off = i - N_X - N_WQ; }
        else if (i < N_X + N_WQ + 2*N_WK)  { src = wv; dst = g_Wvh; off = i - N_X - N_WQ - N_WK; }
        else if (i < CONV_TOTAL)           { src = wo; dst = g_Woh; off = i - N_X - N_WQ - 2*N_WK; }
        else continue;
        float4 v = *(const float4*)(src + off*4);
        uint2 uu; uu.x = f2h2(v.x, v.y); uu.y = f2h2(v.z, v.w);
        *(uint2*)(dst + off*4) = uu;
    }
}

// ---------------- RoPE ------------------------------------------------------
__global__ void rope_table_kernel() {
    int idx = blockIdx.x*blockDim.x + threadIdx.x;
    if (idx >= T_SEQ*64) return;
    int t = idx >> 6, i = idx & 63;
    float inv = powf(10000.0f, -(float)i / 64.0f);
    float ang = (float)t * inv;
    float s, c;
    sincosf(ang, &s, &c);
    g_cos[idx] = c;
    g_sin[idx] = s;
}

#define NQ_ROPE (M_ROWS*HQ*32)
#define NK_ROPE (M_ROWS*HKV*32)
__global__ void rope_qk_kernel(__half* __restrict__ Qh, __half* __restrict__ Kh,
                               float qscale) {
    int idx = blockIdx.x*blockDim.x + threadIdx.x;
    __half* buf; int heads; float scale;
    if (idx < NQ_ROPE)                  { buf = Qh; heads = HQ;  scale = qscale; }
    else if (idx < NQ_ROPE + NK_ROPE)   { buf = Kh; heads = HKV; scale = 1.0f; idx -= NQ_ROPE; }
    else return;
    int i2 = idx & 31;
    int h = (idx >> 5) % heads;
    int m = idx / (32 * heads);
    int t = m & (T_SEQ - 1);
    int d0 = 2*i2;
    uint32_t* p = (uint32_t*)(buf + (size_t)m * heads * HD + h * HD);
    float2 a = __half22float2(*(__half2*)&p[i2]);
    float2 b = __half22float2(*(__half2*)&p[32 + i2]);
    float c0 = g_cos[t*64 + d0], c1 = g_cos[t*64 + d0 + 1];
    float s0 = g_sin[t*64 + d0], s1 = g_sin[t*64 + d0 + 1];
    p[i2]      = f2h2((a.x*c0 - b.x*s0)*scale, (a.y*c1 - b.y*s1)*scale);
    p[32 + i2] = f2h2((b.x*c0 + a.x*s0)*scale, (b.y*c1 + a.y*s1)*scale);
}

// ---------------- wide fp16 GEMM for QKV: 128x256 CTA, 64x64 warp tiles ------
// 8 warps (2 row-groups x 4 col-groups). BK=64, 3-stage cp.async.
// Per k-step per warp: 8 LDSM : 32 HMMA (vs 6:16 in narrow kernel).
#define WASZ 16384                    /* A stage: 128 x 64 fp16 */
#define WBSZ 32768                    /* B stage: 64 x 256 fp16 */
#define WSTG (WASZ + WBSZ)
#define WGEMM_SMEM (3*WSTG)

__global__ __launch_bounds__(256) void hgemm_wide(
    const __half* __restrict__ A,
    const __half* __restrict__ B0, const __half* __restrict__ B1, const __half* __restrict__ B2,
    __half* __restrict__ C0, __half* __restrict__ C1, __half* __restrict__ C2,
    int t0, int t1, int K)
{
    extern __shared__ char gsm[];
    const uint32_t sb = cvta_smem(gsm);

    const int tx = blockIdx.x;
    const __half* B; __half* C; int N, cb;
    if (tx < t0)           { B = B0; C = C0; N = t0*256; cb = tx*256; }
    else if (tx < t0 + t1) { B = B1; C = C1; N = t1*256; cb = (tx - t0)*256; }
    else { B = B2; C = C2; N = ((int)gridDim.x - t0 - t1)*256; cb = (tx - t0 - t1)*256; }

    const int tid = threadIdx.x;
    const int lane = tid & 31, wid = tid >> 5;
    const int gid = lane >> 2, tig = lane & 3;
    const int wm = wid & 1, wn = wid >> 1;     // 2 row-groups x 4 col-groups
    const int bm = blockIdx.y * 128;
    const int nc = K >> 6;

    const int ar = tid >> 3, ac = tid & 7;     // A: rows ar+32i (i<4), 8 chunks/row
    const int bk = tid >> 5, bc = tid & 31;    // B: rows bk+8i (i<8), 32 chunks/row
    const uint32_t aswz = (uint32_t)(ac ^ (ar & 7)) << 4;
    const uint32_t bswz = (uint32_t)((bc & 24) | ((bc ^ (bk & 7)) & 7)) << 4;

    auto issue = [&](int c) {
        const uint32_t sA = sb + (c % 3)*WSTG;
        const uint32_t sB = sA + WASZ;
        const __half* Ag = A + (size_t)(bm + ar)*K + c*64 + ac*8;
        #pragma unroll
        for (int i = 0; i < 4; i++)
            cp16(sA + (uint32_t)(ar + 32*i)*128 + aswz, Ag + (size_t)(32*i)*K);
        const __half* Bg = B + (size_t)(c*64 + bk)*N + cb + bc*8;
        #pragma unroll
        for (int i = 0; i < 8; i++)
            cp16(sB + (uint32_t)(bk + 8*i)*512 + bswz, Bg + (size_t)(8*i)*N);
        CPCOMMIT();
    };

    float acc[4][8][4];
    #pragma unroll
    for (int mt = 0; mt < 4; mt++)
        #pragma unroll
        for (int nt = 0; nt < 8; nt++)
            #pragma unroll
            for (int e = 0; e < 4; e++) acc[mt][nt][e] = 0.f;

    issue(0); issue(1);

    for (int c = 0; c < nc; ++c) {
        if (c + 2 < nc) { CPWAIT1(); } else { CPWAIT0(); }
        __syncthreads();
        if (c + 2 < nc) issue(c + 2);

        const uint32_t sA = sb + (c % 3)*WSTG;
        const uint32_t sB = sA + WASZ;

        #pragma unroll
        for (int ks = 0; ks < 4; ++ks) {
            uint32_t af[4][4];
            #pragma unroll
            for (int mt = 0; mt < 4; mt++) {
                int row = wm*64 + mt*16 + (lane & 15);
                int ch = ks*2 + (lane >> 4);
                ldsm4(af[mt], sA + (uint32_t)row*128 + ((uint32_t)(ch ^ (row & 7)) << 4));
            }
            uint32_t bf[8][2];
            #pragma unroll
            for (int nb = 0; nb < 4; nb++) {
                int kr = ks*16 + (lane & 15);
                int ch = wn*8 + nb*2 + (lane >> 4);
                uint32_t q[4];
                ldsm4t(q, sB + (uint32_t)kr*512 +
                          ((uint32_t)((ch & 24) | ((ch ^ (kr & 7)) & 7)) << 4));
                bf[2*nb][0] = q[0]; bf[2*nb][1] = q[1];
                bf[2*nb+1][0] = q[2]; bf[2*nb+1][1] = q[3];
            }
            #pragma unroll
            for (int mt = 0; mt < 4; mt++)
                #pragma unroll
                for (int nt = 0; nt < 8; nt++)
                    mma16(acc[mt][nt], af[mt], bf[nt]);
        }
    }

    #pragma unroll
    for (int mt = 0; mt < 4; mt++) {
        int r0 = bm + wm*64 + mt*16 + gid;
        #pragma unroll
        for (int nt = 0; nt < 8; nt++) {
            int col = cb + wn*64 + nt*8 + 2*tig;
            *(uint32_t*)(C + (size_t)r0 * N + col)       = f2h2(acc[mt][nt][0], acc[mt][nt][1]);
            *(uint32_t*)(C + (size_t)(r0 + 8) * N + col) = f2h2(acc[mt][nt][2], acc[mt][nt][3]);
        }
    }
}

// ---------------- narrow fp16 GEMM (O-proj): 64x128 CTA, fp32 out -----------
#define GASZ  (64*128)               /* A stage bytes: 64 rows x 64 cols fp16 */
#define GSTG  (GASZ + 16384)
#define GEMM_SMEM (3*GSTG)

__global__ __launch_bounds__(256) void hgemm_n(
    const __half* __restrict__ A, const __half* __restrict__ B,
    float* __restrict__ C, int N, int K)
{
    extern __shared__ char gsm[];
    const uint32_t sb = cvta_smem(gsm);

    const int cb = blockIdx.x * 128;
    const int tid = threadIdx.x;
    const int lane = tid & 31, wid = tid >> 5;
    const int gid = lane >> 2, tig = lane & 3;
    const int wm = wid & 3, wn = wid >> 2;
    const int bm = blockIdx.y * 64;
    const int nc = K >> 6;

    const int ar = tid >> 3, ac = tid & 7;
    const int bk = tid >> 4, bc = tid & 15;
    const uint32_t aswz = (uint32_t)(ac ^ (ar & 7)) << 4;
    const uint32_t bswz = (uint32_t)((bc & 8) | ((bc ^ (bk & 7)) & 7)) << 4;

    auto issue = [&](int c) {
        const uint32_t sA = sb + (c % 3)*GSTG;
        const uint32_t sB = sA + GASZ;
        const __half* Ag = A + (size_t)(bm + ar)*K + c*64 + ac*8;
        #pragma unroll
        for (int i = 0; i < 2; i++)
            cp16(sA + (uint32_t)(ar + 32*i)*128 + aswz, Ag + (size_t)(32*i)*K);
        const __half* Bg = B + (size_t)(c*64 + bk)*N + cb + bc*8;
        #pragma unroll
        for (int i = 0; i < 4; i++)
            cp16(sB + (uint32_t)(bk + 16*i)*256 + bswz, Bg + (size_t)(16*i)*N);
        CPCOMMIT();
    };

    float acc[8][4];
    #pragma unroll
    for (int nt = 0; nt < 8; nt++)
        #pragma unroll
        for (int e = 0; e < 4; e++) acc[nt][e] = 0.f;

    issue(0); issue(1);

    for (int c = 0; c < nc; ++c) {
        if (c + 2 < nc) { CPWAIT1(); } else { CPWAIT0(); }
        __syncthreads();
        if (c + 2 < nc) issue(c + 2);

        const uint32_t sA = sb + (c % 3)*GSTG;
        const uint32_t sB = sA + GASZ;

        #pragma unroll
        for (int ks = 0; ks < 4; ++ks) {
            uint32_t af[4];
            {
                int row = wm*16 + (lane & 15);
                int ch = ks*2 + (lane >> 4);
                ldsm4(af, sA + (uint32_t)row*128 + ((uint32_t)(ch ^ (row & 7)) << 4));
            }
            uint32_t bf[8][2];
            #pragma unroll
            for (int nb = 0; nb < 4; nb++) {
                int kr = ks*16 + (lane & 15);
                int ch = wn*8 + nb*2 + (lane >> 4);
                uint32_t q[4];
                ldsm4t(q, sB + (uint32_t)kr*256 +
                          ((uint32_t)((ch & 8) | ((ch ^ (kr & 7)) & 7)) << 4));
                bf[2*nb][0] = q[0]; bf[2*nb][1] = q[1];
                bf[2*nb+1][0] = q[2]; bf[2*nb+1][1] = q[3];
            }
            #pragma unroll
            for (int nt = 0; nt < 8; nt++)
                mma16(acc[nt], af, bf[nt]);
        }
    }

    int r0 = bm + wm*16 + gid;
    #pragma unroll
    for (int nt = 0; nt < 8; nt++) {
        int col = cb + wn*64 + nt*8 + 2*tig;
        *(float2*)(C + (size_t)r0 * N + col)       = make_float2(acc[nt][0], acc[nt][1]);
        *(float2*)(C + (size_t)(r0 + 8) * N + col) = make_float2(acc[nt][2], acc[nt][3]);
    }
}

// ---------------- flash attention: BQ=64, 4 warps, 2 CTAs/SM ----------------
#define FKVSTB 32768
#define FQSZ   16384
#define FLASH_SMEM (FQSZ + 3*FKVSTB)

__global__ __launch_bounds__(128) void flash_h2(
    const __half* __restrict__ Qh, const __half* __restrict__ Kh,
    const __half* __restrict__ Vh, __half* __restrict__ AOh)
{
    extern __shared__ char fsm[];
    const uint32_t sb = cvta_smem(fsm);
    const int tid = threadIdx.x, lane = tid & 31, wid = tid >> 5;
    const int gid = lane >> 2, tig = lane & 3;
    const int qt = 31 - blockIdx.x;
    const int h = blockIdx.y, b = blockIdx.z;
    const int hk = h >> 2;
    const int wrow = wid * 16;
    const int q0 = b*T_SEQ + qt*64;
    const int nkt = qt + 1;

    uint32_t kvo[8]; uint32_t go[8];
    #pragma unroll
    for (int i = 0; i < 8; i++) {
        int id = tid + 128*i;
        int r = id >> 4, c = id & 15;
        kvo[i] = (uint32_t)r*256 + ((uint32_t)((c & 8) | ((c ^ (r & 7)) & 7)) << 4);
        go[i]  = (uint32_t)(r*DKV + c*8);
    }

    const __half* Kbase = Kh + (size_t)(b*T_SEQ)*DKV + hk*HD;
    const __half* Vbase = Vh + (size_t)(b*T_SEQ)*DKV + hk*HD;

    auto issue_kv = [&](int kt) {
        const uint32_t sK = sb + FQSZ + (kt % 3)*FKVSTB;
        const uint32_t sV = sK + 16384;
        const __half* Kg = Kbase + (size_t)(kt*64)*DKV;
        const __half* Vg = Vbase + (size_t)(kt*64)*DKV;
        #pragma unroll
        for (int i = 0; i < 8; i++) {
            cp16(sK + kvo[i], Kg + go[i]);
            cp16(sV + kvo[i], Vg + go[i]);
        }
        CPCOMMIT();
    };

    {
        const __half* Qg = Qh + (size_t)q0*DMODEL + h*HD;
        #pragma unroll
        for (int i = 0; i < 8; i++) {
            int id = tid + 128*i;
            int r = id >> 4;
            cp16(sb + kvo[i], Qg + (size_t)r*DMODEL + (id & 15)*8);
        }
        const uint32_t sK = sb + FQSZ, sV = sK + 16384;
        #pragma unroll
        for (int i = 0; i < 8; i++) {
            cp16(sK + kvo[i], Kbase + go[i]);
            cp16(sV + kvo[i], Vbase + go[i]);
        }
        CPCOMMIT();
        issue_kv(1);
    }

    float oacc[16][4];
    #pragma unroll
    for (int nt = 0; nt < 16; nt++)
        #pragma unroll
        for (int e = 0; e < 4; e++) oacc[nt][e] = 0.f;
    float l0 = 0.f, l1 = 0.f;

    uint32_t qf[8][4];
    bool qloaded = false;

    for (int kt = 0; kt < nkt; ++kt) {
        if (kt + 2 < nkt) { CPWAIT1(); } else { CPWAIT0(); }
        __syncthreads();
        if (kt + 2 < nkt) issue_kv(kt + 2);

        if (!qloaded) {
            #pragma unroll
            for (int ks = 0; ks < 8; ++ks) {
                int row = wrow + (lane & 15);
                int ch = ks*2 + (lane >> 4);
                ldsm4(qf[ks], sb + (uint32_t)row*256 +
                          ((uint32_t)((ch & 8) | ((ch ^ (row & 7)) & 7)) << 4));
            }
            qloaded = true;
        }

        const uint32_t sK = sb + FQSZ + (kt % 3)*FKVSTB;
        const uint32_t sV = sK + 16384;

        float sacc[8][4];
        #pragma unroll
        for (int nt = 0; nt < 8; nt++)
            #pragma unroll
            for (int e = 0; e < 4; e++) sacc[nt][e] = 0.f;

        #pragma unroll
        for (int ks = 0; ks < 8; ++ks) {
            #pragma unroll
            for (int np = 0; np < 4; np++) {
                int row = np*16 + (lane & 15);
                int ch = ks*2 + (lane >> 4);
                uint32_t q[4];
                ldsm4(q, sK + (uint32_t)row*256 +
                          ((uint32_t)((ch & 8) | ((ch ^ (row & 7)) & 7)) << 4));
                uint32_t bf0[2] = {q[0], q[2]}, bf1[2] = {q[1], q[3]};
                mma16(sacc[2*np],   qf[ks], bf0);
                mma16(sacc[2*np+1], qf[ks], bf1);
            }
        }

        const int qg0 = qt*64 + wrow + gid;
        const int kb  = kt*64;
        uint32_t pf[4][4];
        auto do_exp = [&](bool masked) {
            #pragma unroll
            for (int k2 = 0; k2 < 4; ++k2) {
                float p[2][4];
                #pragma unroll
                for (int j = 0; j < 2; j++) {
                    int nt = 2*k2 + j;
                    int c0 = kb + nt*8 + 2*tig;
                    if (masked) {
                        p[j][0] = (c0     <= qg0    ) ? exp2f(sacc[nt][0]) : 0.f;
                        p[j][1] = (c0 + 1 <= qg0    ) ? exp2f(sacc[nt][1]) : 0.f;
                        p[j][2] = (c0     <= qg0 + 8) ? exp2f(sacc[nt][2]) : 0.f;
                        p[j][3] = (c0 + 1 <= qg0 + 8) ? exp2f(sacc[nt][3]) : 0.f;
                    } else {
                        p[j][0] = exp2f(sacc[nt][0]);
                        p[j][1] = exp2f(sacc[nt][1]);
                        p[j][2] = exp2f(sacc[nt][2]);
                        p[j][3] = exp2f(sacc[nt][3]);
                    }
                }
                pf[k2][0] = f2h2(p[0][0], p[0][1]);
                pf[k2][1] = f2h2(p[0][2], p[0][3]);
                pf[k2][2] = f2h2(p[1][0], p[1][1]);
                pf[k2][3] = f2h2(p[1][2], p[1][3]);
                float2 t;
                t = __half22float2(*(__half2*)&pf[k2][0]); l0 += t.x + t.y;
                t = __half22float2(*(__half2*)&pf[k2][2]); l0 += t.x + t.y;
                t = __half22float2(*(__half2*)&pf[k2][1]); l1 += t.x + t.y;
                t = __half22float2(*(__half2*)&pf[k2][3]); l1 += t.x + t.y;
            }
        };
        if (kt == qt) do_exp(true); else do_exp(false);

        #pragma unroll
        for (int k2 = 0; k2 < 4; ++k2) {
            #pragma unroll
            for (int nb = 0; nb < 8; nb++) {
                int kr = k2*16 + (lane & 15);
                int ch = nb*2 + (lane >> 4);
                uint32_t q[4];
                ldsm4t(q, sV + (uint32_t)kr*256 +
                          ((uint32_t)((ch & 8) | ((ch ^ (kr & 7)) & 7)) << 4));
                uint32_t bf0[2] = {q[0], q[1]}, bf1[2] = {q[2], q[3]};
                mma16(oacc[2*nb],   pf[k2], bf0);
                mma16(oacc[2*nb+1], pf[k2], bf1);
            }
        }
    }

    l0 += __shfl_xor_sync(0xffffffff, l0, 1);
    l0 += __shfl_xor_sync(0xffffffff, l0, 2);
    l1 += __shfl_xor_sync(0xffffffff, l1, 1);
    l1 += __shfl_xor_sync(0xffffffff, l1, 2);
    const float inv0 = 1.f / l0, inv1 = 1.f / l1;

    const int r0 = q0 + wrow + gid;
    #pragma unroll
    for (int nt = 0; nt < 16; nt++) {
        int col = h*HD + nt*8 + 2*tig;
        *(uint32_t*)(AOh + (size_t)r0 * DMODEL + col) =
            f2h2(oacc[nt][0]*inv0, oacc[nt][1]*inv0);
        *(uint32_t*)(AOh + (size_t)(r0 + 8) * DMODEL + col) =
            f2h2(oacc[nt][2]*inv1, oacc[nt][3]*inv1);
    }
}

// ---------------- launch -----------------------------------------------------
extern "C" void kernel_launch(void* const* d_in, const int* in_sizes, int n_in,
                              void* d_out, int out_size)
{
    const float* x  = (const float*)d_in[0];
    const float* Wq = (const float*)d_in[1];
    const float* Wk = (const float*)d_in[2];
    const float* Wv = (const float*)d_in[3];
    const float* Wo = (const float*)d_in[4];
    float* out = (float*)d_out;

    __half *xh, *Wqh, *Wkh, *Wvh, *Woh, *Qh, *Kh, *Vh, *AOh;
    cudaGetSymbolAddress((void**)&xh,  g_xh);
    cudaGetSymbolAddress((void**)&Wqh, g_Wqh);
    cudaGetSymbolAddress((void**)&Wkh, g_Wkh);
    cudaGetSymbolAddress((void**)&Wvh, g_Wvh);
    cudaGetSymbolAddress((void**)&Woh, g_Woh);
    cudaGetSymbolAddress((void**)&Qh,  g_Qh);
    cudaGetSymbolAddress((void**)&Kh,  g_Kh);
    cudaGetSymbolAddress((void**)&Vh,  g_Vh);
    cudaGetSymbolAddress((void**)&AOh, g_AOh);

    cudaFuncSetAttribute(hgemm_wide, cudaFuncAttributeMaxDynamicSharedMemorySize, WGEMM_SMEM);
    cudaFuncSetAttribute(hgemm_n,    cudaFuncAttributeMaxDynamicSharedMemorySize, GEMM_SMEM);
    cudaFuncSetAttribute(flash_h2,   cudaFuncAttributeMaxDynamicSharedMemorySize, FLASH_SMEM);

    rope_table_kernel<<<(T_SEQ*64 + 255)/256, 256>>>();
    conv_all<<<(int)((CONV_TOTAL + 1023)/1024), 256>>>(x, Wq, Wk, Wv, Wo);

    // fused QKV projection (fp16 out), 256-wide tiles:
    // tiles 0-7 -> Q (N=2048), 8-9 -> K (N=512), 10-11 -> V (N=512)
    hgemm_wide<<<dim3(12, M_ROWS/128), 256, WGEMM_SMEM>>>(
        xh, Wqh, Wkh, Wvh, Qh, Kh, Vh, 8, 2, DMODEL);

    // in-place RoPE on Q and K in one launch; Q pre-scaled by FA_SCALE*log2(e)
    rope_qk_kernel<<<(NQ_ROPE + NK_ROPE + 255)/256, 256>>>(Qh, Kh, FA_SCALE*LOG2E);

    flash_h2<<<dim3(32, HQ, BATCH), 128, FLASH_SMEM>>>(Qh, Kh, Vh, AOh);

    // output projection (fp32 out), 64x128 tiles: 1024 CTAs
    hgemm_n<<<dim3(DMODEL/128, M_ROWS/64), 256, GEMM_SMEM>>>(
        AOh, Woh, out, DMODEL, DMODEL);
}

// round 13
// speedup vs baseline: 1.0385x; 1.0385x over previous
#include <cuda_runtime.h>
#include <cuda_fp16.h>
#include <math.h>
#include <stdint.h>

#define T_SEQ 2048
#define BATCH 2
#define DMODEL 2048
#define HQ 16
#define HKV 4
#define HD 128
#define M_ROWS (BATCH*T_SEQ)   /* 4096 */
#define DKV (HKV*HD)           /* 512 */
#define FA_SCALE 0.08838834764831845f
#define LOG2E 1.4426950408889634f

// ---------------- scratch ---------------------------------------------------
__device__ __half g_xh[M_ROWS*DMODEL];
__device__ __half g_Wqh[DMODEL*DMODEL];
__device__ __half g_Wkh[DMODEL*DKV];
__device__ __half g_Wvh[DMODEL*DKV];
__device__ __half g_Woh[DMODEL*DMODEL];
__device__ __half g_Qh[M_ROWS*DMODEL];
__device__ __half g_Kh[M_ROWS*DKV];
__device__ __half g_Vh[M_ROWS*DKV];
__device__ __half g_AOh[M_ROWS*DMODEL];
__device__ float  g_cos[T_SEQ*64];
__device__ float  g_sin[T_SEQ*64];

// ---------------- helpers ----------------------------------------------------
__device__ __forceinline__ uint32_t f2h2(float a, float b) {
    __half2 h = __halves2half2(__float2half_rn(a), __float2half_rn(b));
    return *reinterpret_cast<uint32_t*>(&h);
}
__device__ __forceinline__ uint32_t cvta_smem(const void* p) {
    uint32_t a;
    asm("{ .reg .u64 t; cvta.to.shared.u64 t, %1; cvt.u32.u64 %0, t; }"
        : "=r"(a) : "l"(p));
    return a;
}
__device__ __forceinline__ void mma16(float* d, const uint32_t* a, const uint32_t* b) {
    asm volatile("mma.sync.aligned.m16n8k16.row.col.f32.f16.f16.f32 "
        "{%0,%1,%2,%3}, {%4,%5,%6,%7}, {%8,%9}, {%0,%1,%2,%3};"
        : "+f"(d[0]), "+f"(d[1]), "+f"(d[2]), "+f"(d[3])
        : "r"(a[0]), "r"(a[1]), "r"(a[2]), "r"(a[3]), "r"(b[0]), "r"(b[1]));
}
__device__ __forceinline__ void ldsm4(uint32_t* r, uint32_t a) {
    asm volatile("ldmatrix.sync.aligned.m8n8.x4.shared.b16 {%0,%1,%2,%3}, [%4];"
        : "=r"(r[0]), "=r"(r[1]), "=r"(r[2]), "=r"(r[3]) : "r"(a));
}
__device__ __forceinline__ void ldsm4t(uint32_t* r, uint32_t a) {
    asm volatile("ldmatrix.sync.aligned.m8n8.x4.trans.shared.b16 {%0,%1,%2,%3}, [%4];"
        : "=r"(r[0]), "=r"(r[1]), "=r"(r[2]), "=r"(r[3]) : "r"(a));
}
__device__ __forceinline__ void cp16(uint32_t dst, const void* src) {
    asm volatile("cp.async.cg.shared.global [%0], [%1], 16;" :: "r"(dst), "l"(src));
}
#define CPCOMMIT() asm volatile("cp.async.commit_group;" ::: "memory")
#define CPWAIT1()  asm volatile("cp.async.wait_group 1;" ::: "memory")
#define CPWAIT0()  asm volatile("cp.async.wait_group 0;" ::: "memory")

// ---------------- conv (fp32->fp16, 4 float4/thread) + rope table fused ------
#define N_X  ((long)M_ROWS*DMODEL/4)
#define N_WQ ((long)DMODEL*DMODEL/4)
#define N_WK ((long)DMODEL*DKV/4)
#define CONV_TOTAL (N_X + 2*N_WQ + 2*N_WK)
#define NCONV_BLK ((int)((CONV_TOTAL + 1023)/1024))
#define NTAB_BLK  ((T_SEQ*64)/256)

__global__ void conv_table(const float* __restrict__ x, const float* __restrict__ wq,
                           const float* __restrict__ wk, const float* __restrict__ wv,
                           const float* __restrict__ wo) {
    if ((int)blockIdx.x >= NCONV_BLK) {
        int idx = ((int)blockIdx.x - NCONV_BLK)*256 + threadIdx.x;
        int t = idx >> 6, i = idx & 63;
        float inv = powf(10000.0f, -(float)i / 64.0f);
        float ang = (float)t * inv;
        float s, c;
        sincosf(ang, &s, &c);
        g_cos[idx] = c;
        g_sin[idx] = s;
        return;
    }
    long base = (long)blockIdx.x*1024 + threadIdx.x;
    #pragma unroll
    for (int u = 0; u < 4; u++) {
        long i = base + u*256;
        const float* src; __half* dst; long off;
        if (i < N_X)                       { src = x;  dst = g_xh;  off = i; }
        else if (i < N_X + N_WQ)           { src = wq; dst = g_Wqh; off = i - N_X; }
        else if (i < N_X + N_WQ + N_WK)    { src = wk; dst = g_Wkh; off = i - N_X - N_WQ; }
        else if (i < N_X + N_WQ + 2*N_WK)  { src = wv; dst = g_Wvh; off = i - N_X - N_WQ - N_WK; }
        else if (i < CONV_TOTAL)           { src = wo; dst = g_Woh; off = i - N_X - N_WQ - 2*N_WK; }
        else continue;
        float4 v = *(const float4*)(src + off*4);
        uint2 uu; uu.x = f2h2(v.x, v.y); uu.y = f2h2(v.z, v.w);
        *(uint2*)(dst + off*4) = uu;
    }
}

// ---------------- in-place fp16 RoPE on K only -------------------------------
#define NK_ROPE (M_ROWS*HKV*32)
__global__ void rope_k_kernel(__half* __restrict__ Kh) {
    int idx = blockIdx.x*blockDim.x + threadIdx.x;
    if (idx >= NK_ROPE) return;
    int i2 = idx & 31;
    int h = (idx >> 5) % HKV;
    int m = idx / (32 * HKV);
    int t = m & (T_SEQ - 1);
    int d0 = 2*i2;
    uint32_t* p = (uint32_t*)(Kh + (size_t)m * DKV + h * HD);
    float2 a = __half22float2(*(__half2*)&p[i2]);
    float2 b = __half22float2(*(__half2*)&p[32 + i2]);
    float c0 = g_cos[t*64 + d0], c1 = g_cos[t*64 + d0 + 1];
    float s0 = g_sin[t*64 + d0], s1 = g_sin[t*64 + d0 + 1];
    p[i2]      = f2h2(a.x*c0 - b.x*s0, a.y*c1 - b.y*s1);
    p[32 + i2] = f2h2(b.x*c0 + a.x*s0, b.y*c1 + a.y*s1);
}

// ---------------- fp16 GEMM: cp.async 3-stage + ldmatrix, MTILE templated ----
#define GASZ(MT)  (64*(MT)*128)
#define GSTG(MT)  (GASZ(MT) + 16384)
#define GEMM_SMEM(MT) (3*GSTG(MT))

template<int MT>
__global__ __launch_bounds__(256) void hgemm(
    const __half* __restrict__ A,
    const __half* __restrict__ B0, const __half* __restrict__ B1, const __half* __restrict__ B2,
    void* __restrict__ C0, void* __restrict__ C1, void* __restrict__ C2,
    int t0, int t1, int K, int half_out)
{
    extern __shared__ char gsm[];
    const uint32_t sb = cvta_smem(gsm);

    const int tx = blockIdx.x;
    const __half* B; void* C; int N, cb;
    if (tx < t0)           { B = B0; C = C0; N = t0*128; cb = tx*128; }
    else if (tx < t0 + t1) { B = B1; C = C1; N = t1*128; cb = (tx - t0)*128; }
    else { B = B2; C = C2; N = ((int)gridDim.x - t0 - t1)*128; cb = (tx - t0 - t1)*128; }

    const int tid = threadIdx.x;
    const int lane = tid & 31, wid = tid >> 5;
    const int gid = lane >> 2, tig = lane & 3;
    const int wm = wid & 3, wn = wid >> 2;
    const int bm = blockIdx.y * (64*MT);
    const int nc = K >> 6;

    const int ar = tid >> 3, ac = tid & 7;
    const int bk = tid >> 4, bc = tid & 15;
    const uint32_t aswz = (uint32_t)(ac ^ (ar & 7)) << 4;
    const uint32_t bswz = (uint32_t)((bc & 8) | ((bc ^ (bk & 7)) & 7)) << 4;

    auto issue = [&](int c) {
        const uint32_t sA = sb + (c % 3)*GSTG(MT);
        const uint32_t sB = sA + GASZ(MT);
        const __half* Ag = A + (size_t)(bm + ar)*K + c*64 + ac*8;
        #pragma unroll
        for (int i = 0; i < 2*MT; i++)
            cp16(sA + (uint32_t)(ar + 32*i)*128 + aswz, Ag + (size_t)(32*i)*K);
        const __half* Bg = B + (size_t)(c*64 + bk)*N + cb + bc*8;
        #pragma unroll
        for (int i = 0; i < 4; i++)
            cp16(sB + (uint32_t)(bk + 16*i)*256 + bswz, Bg + (size_t)(16*i)*N);
        CPCOMMIT();
    };

    float acc[MT][8][4];
    #pragma unroll
    for (int mt = 0; mt < MT; mt++)
        #pragma unroll
        for (int nt = 0; nt < 8; nt++)
            #pragma unroll
            for (int e = 0; e < 4; e++) acc[mt][nt][e] = 0.f;

    issue(0); issue(1);

    for (int c = 0; c < nc; ++c) {
        if (c + 2 < nc) { CPWAIT1(); } else { CPWAIT0(); }
        __syncthreads();
        if (c + 2 < nc) issue(c + 2);

        const uint32_t sA = sb + (c % 3)*GSTG(MT);
        const uint32_t sB = sA + GASZ(MT);

        #pragma unroll
        for (int ks = 0; ks < 4; ++ks) {
            uint32_t af[MT][4];
            #pragma unroll
            for (int mt = 0; mt < MT; mt++) {
                int row = wm*(16*MT) + mt*16 + (lane & 15);
                int ch = ks*2 + (lane >> 4);
                ldsm4(af[mt], sA + (uint32_t)row*128 + ((uint32_t)(ch ^ (row & 7)) << 4));
            }
            uint32_t bf[8][2];
            #pragma unroll
            for (int nb = 0; nb < 4; nb++) {
                int kr = ks*16 + (lane & 15);
                int ch = wn*8 + nb*2 + (lane >> 4);
                uint32_t q[4];
                ldsm4t(q, sB + (uint32_t)kr*256 +
                          ((uint32_t)((ch & 8) | ((ch ^ (kr & 7)) & 7)) << 4));
                bf[2*nb][0] = q[0]; bf[2*nb][1] = q[1];
                bf[2*nb+1][0] = q[2]; bf[2*nb+1][1] = q[3];
            }
            #pragma unroll
            for (int mt = 0; mt < MT; mt++)
                #pragma unroll
                for (int nt = 0; nt < 8; nt++)
                    mma16(acc[mt][nt], af[mt], bf[nt]);
        }
    }

    if (half_out) {
        __half* Ch = (__half*)C;
        #pragma unroll
        for (int mt = 0; mt < MT; mt++) {
            int r0 = bm + wm*(16*MT) + mt*16 + gid;
            #pragma unroll
            for (int nt = 0; nt < 8; nt++) {
                int col = cb + wn*64 + nt*8 + 2*tig;
                *(uint32_t*)(Ch + (size_t)r0 * N + col)       = f2h2(acc[mt][nt][0], acc[mt][nt][1]);
                *(uint32_t*)(Ch + (size_t)(r0 + 8) * N + col) = f2h2(acc[mt][nt][2], acc[mt][nt][3]);
            }
        }
    } else {
        float* Cf = (float*)C;
        #pragma unroll
        for (int mt = 0; mt < MT; mt++) {
            int r0 = bm + wm*(16*MT) + mt*16 + gid;
            #pragma unroll
            for (int nt = 0; nt < 8; nt++) {
                int col = cb + wn*64 + nt*8 + 2*tig;
                *(float2*)(Cf + (size_t)r0 * N + col)       = make_float2(acc[mt][nt][0], acc[mt][nt][1]);
                *(float2*)(Cf + (size_t)(r0 + 8) * N + col) = make_float2(acc[mt][nt][2], acc[mt][nt][3]);
            }
        }
    }
}

// ---------------- flash attention: BQ=64, 4 warps, Q-RoPE fused in prologue --
#define FKVSTB 32768
#define FQSZ   16384
#define FLASH_SMEM (FQSZ + 3*FKVSTB)

__global__ __launch_bounds__(128) void flash_h2(
    const __half* __restrict__ Qh, const __half* __restrict__ Kh,
    const __half* __restrict__ Vh, __half* __restrict__ AOh)
{
    extern __shared__ char fsm[];
    const uint32_t sb = cvta_smem(fsm);
    const int tid = threadIdx.x, lane = tid & 31, wid = tid >> 5;
    const int gid = lane >> 2, tig = lane & 3;
    const int qt = 31 - blockIdx.x;
    const int h = blockIdx.y, b = blockIdx.z;
    const int hk = h >> 2;
    const int wrow = wid * 16;
    const int q0 = b*T_SEQ + qt*64;
    const int nkt = qt + 1;

    uint32_t kvo[8]; uint32_t go[8];
    #pragma unroll
    for (int i = 0; i < 8; i++) {
        int id = tid + 128*i;
        int r = id >> 4, c = id & 15;
        kvo[i] = (uint32_t)r*256 + ((uint32_t)((c & 8) | ((c ^ (r & 7)) & 7)) << 4);
        go[i]  = (uint32_t)(r*DKV + c*8);
    }

    const __half* Kbase = Kh + (size_t)(b*T_SEQ)*DKV + hk*HD;
    const __half* Vbase = Vh + (size_t)(b*T_SEQ)*DKV + hk*HD;

    auto issue_kv = [&](int kt) {
        const uint32_t sK = sb + FQSZ + (kt % 3)*FKVSTB;
        const uint32_t sV = sK + 16384;
        const __half* Kg = Kbase + (size_t)(kt*64)*DKV;
        const __half* Vg = Vbase + (size_t)(kt*64)*DKV;
        #pragma unroll
        for (int i = 0; i < 8; i++) {
            cp16(sK + kvo[i], Kg + go[i]);
            cp16(sV + kvo[i], Vg + go[i]);
        }
        CPCOMMIT();
    };

    // KV(0) as group 0, KV(1) as group 1 (start DMA first)
    {
        const uint32_t sK = sb + FQSZ, sV = sK + 16384;
        #pragma unroll
        for (int i = 0; i < 8; i++) {
            cp16(sK + kvo[i], Kbase + go[i]);
            cp16(sV + kvo[i], Vbase + go[i]);
        }
        CPCOMMIT();
        issue_kv(1);
    }

    // Q prologue with fused RoPE: thread -> row r = tid>>1, dim-quarter = tid&1.
    // Reads unroped fp16 Q, rotates pairs (d, d+64) in fp32, scales, stores fp16
    // into the SAME swizzled smem layout the cp.async path used.
    {
        const int r  = tid >> 1;
        const int db = (tid & 1) * 32;              // dims [db, db+32)
        const int t  = qt*64 + r;                   // position within sequence
        const __half* Qrow = Qh + (size_t)(q0 + r)*DMODEL + h*HD;
        const float qs = FA_SCALE * LOG2E;
        #pragma unroll
        for (int c4 = 0; c4 < 4; ++c4) {
            int d = db + c4*8;                      // 8 dims per step
            uint4 lo4 = *(const uint4*)(Qrow + d);
            uint4 hi4 = *(const uint4*)(Qrow + d + 64);
            const __half* lh = (const __half*)&lo4;
            const __half* hh = (const __half*)&hi4;
            float4 ca = *(const float4*)(g_cos + t*64 + d);
            float4 cbv = *(const float4*)(g_cos + t*64 + d + 4);
            float4 sa = *(const float4*)(g_sin + t*64 + d);
            float4 sbv = *(const float4*)(g_sin + t*64 + d + 4);
            float cc[8] = {ca.x, ca.y, ca.z, ca.w, cbv.x, cbv.y, cbv.z, cbv.w};
            float ss[8] = {sa.x, sa.y, sa.z, sa.w, sbv.x, sbv.y, sbv.z, sbv.w};
            float lo[8], hi[8];
            #pragma unroll
            for (int j = 0; j < 8; j++) {
                float a = __half2float(lh[j]);
                float bb = __half2float(hh[j]);
                lo[j] = (a*cc[j] - bb*ss[j]) * qs;
                hi[j] = (bb*cc[j] + a*ss[j]) * qs;
            }
            uint4 wlo, whi;
            wlo.x = f2h2(lo[0], lo[1]); wlo.y = f2h2(lo[2], lo[3]);
            wlo.z = f2h2(lo[4], lo[5]); wlo.w = f2h2(lo[6], lo[7]);
            whi.x = f2h2(hi[0], hi[1]); whi.y = f2h2(hi[2], hi[3]);
            whi.z = f2h2(hi[4], hi[5]); whi.w = f2h2(hi[6], hi[7]);
            int c = d >> 3;                         // chunk 0..7 (lower)
            uint32_t swz = (uint32_t)((c ^ (r & 7)) & 7) << 4;
            *(uint4*)(fsm + (uint32_t)r*256 + swz) = wlo;
            *(uint4*)(fsm + (uint32_t)r*256 + (swz | 128)) = whi;  // chunk c+8
        }
    }

    float oacc[16][4];
    #pragma unroll
    for (int nt = 0; nt < 16; nt++)
        #pragma unroll
        for (int e = 0; e < 4; e++) oacc[nt][e] = 0.f;
    float l0 = 0.f, l1 = 0.f;

    uint32_t qf[8][4];
    bool qloaded = false;

    for (int kt = 0; kt < nkt; ++kt) {
        if (kt + 2 < nkt) { CPWAIT1(); } else { CPWAIT0(); }
        __syncthreads();
        if (kt + 2 < nkt) issue_kv(kt + 2);

        if (!qloaded) {
            #pragma unroll
            for (int ks = 0; ks < 8; ++ks) {
                int row = wrow + (lane & 15);
                int ch = ks*2 + (lane >> 4);
                ldsm4(qf[ks], sb + (uint32_t)row*256 +
                          ((uint32_t)((ch & 8) | ((ch ^ (row & 7)) & 7)) << 4));
            }
            qloaded = true;
        }

        const uint32_t sK = sb + FQSZ + (kt % 3)*FKVSTB;
        const uint32_t sV = sK + 16384;

        float sacc[8][4];
        #pragma unroll
        for (int nt = 0; nt < 8; nt++)
            #pragma unroll
            for (int e = 0; e < 4; e++) sacc[nt][e] = 0.f;

        #pragma unroll
        for (int ks = 0; ks < 8; ++ks) {
            #pragma unroll
            for (int np = 0; np < 4; np++) {
                int row = np*16 + (lane & 15);
                int ch = ks*2 + (lane >> 4);
                uint32_t q[4];
                ldsm4(q, sK + (uint32_t)row*256 +
                          ((uint32_t)((ch & 8) | ((ch ^ (row & 7)) & 7)) << 4));
                uint32_t bf0[2] = {q[0], q[2]}, bf1[2] = {q[1], q[3]};
                mma16(sacc[2*np],   qf[ks], bf0);
                mma16(sacc[2*np+1], qf[ks], bf1);
            }
        }

        const int qg0 = qt*64 + wrow + gid;
        const int kb  = kt*64;
        uint32_t pf[4][4];
        auto do_exp = [&](bool masked) {
            #pragma unroll
            for (int k2 = 0; k2 < 4; ++k2) {
                float p[2][4];
                #pragma unroll
                for (int j = 0; j < 2; j++) {
                    int nt = 2*k2 + j;
                    int c0 = kb + nt*8 + 2*tig;
                    if (masked) {
                        p[j][0] = (c0     <= qg0    ) ? exp2f(sacc[nt][0]) : 0.f;
                        p[j][1] = (c0 + 1 <= qg0    ) ? exp2f(sacc[nt][1]) : 0.f;
                        p[j][2] = (c0     <= qg0 + 8) ? exp2f(sacc[nt][2]) : 0.f;
                        p[j][3] = (c0 + 1 <= qg0 + 8) ? exp2f(sacc[nt][3]) : 0.f;
                    } else {
                        p[j][0] = exp2f(sacc[nt][0]);
                        p[j][1] = exp2f(sacc[nt][1]);
                        p[j][2] = exp2f(sacc[nt][2]);
                        p[j][3] = exp2f(sacc[nt][3]);
                    }
                }
                pf[k2][0] = f2h2(p[0][0], p[0][1]);
                pf[k2][1] = f2h2(p[0][2], p[0][3]);
                pf[k2][2] = f2h2(p[1][0], p[1][1]);
                pf[k2][3] = f2h2(p[1][2], p[1][3]);
                float2 t;
                t = __half22float2(*(__half2*)&pf[k2][0]); l0 += t.x + t.y;
                t = __half22float2(*(__half2*)&pf[k2][2]); l0 += t.x + t.y;
                t = __half22float2(*(__half2*)&pf[k2][1]); l1 += t.x + t.y;
                t = __half22float2(*(__half2*)&pf[k2][3]); l1 += t.x + t.y;
            }
        };
        if (kt == qt) do_exp(true); else do_exp(false);

        #pragma unroll
        for (int k2 = 0; k2 < 4; ++k2) {
            #pragma unroll
            for (int nb = 0; nb < 8; nb++) {
                int kr = k2*16 + (lane & 15);
                int ch = nb*2 + (lane >> 4);
                uint32_t q[4];
                ldsm4t(q, sV + (uint32_t)kr*256 +
                          ((uint32_t)((ch & 8) | ((ch ^ (kr & 7)) & 7)) << 4));
                uint32_t bf0[2] = {q[0], q[1]}, bf1[2] = {q[2], q[3]};
                mma16(oacc[2*nb],   pf[k2], bf0);
                mma16(oacc[2*nb+1], pf[k2], bf1);
            }
        }
    }

    l0 += __shfl_xor_sync(0xffffffff, l0, 1);
    l0 += __shfl_xor_sync(0xffffffff, l0, 2);
    l1 += __shfl_xor_sync(0xffffffff, l1, 1);
    l1 += __shfl_xor_sync(0xffffffff, l1, 2);
    const float inv0 = 1.f / l0, inv1 = 1.f / l1;

    const int r0 = q0 + wrow + gid;
    #pragma unroll
    for (int nt = 0; nt < 16; nt++) {
        int col = h*HD + nt*8 + 2*tig;
        *(uint32_t*)(AOh + (size_t)r0 * DMODEL + col) =
            f2h2(oacc[nt][0]*inv0, oacc[nt][1]*inv0);
        *(uint32_t*)(AOh + (size_t)(r0 + 8) * DMODEL + col) =
            f2h2(oacc[nt][2]*inv1, oacc[nt][3]*inv1);
    }
}

// ---------------- launch -----------------------------------------------------
extern "C" void kernel_launch(void* const* d_in, const int* in_sizes, int n_in,
                              void* d_out, int out_size)
{
    const float* x  = (const float*)d_in[0];
    const float* Wq = (const float*)d_in[1];
    const float* Wk = (const float*)d_in[2];
    const float* Wv = (const float*)d_in[3];
    const float* Wo = (const float*)d_in[4];
    float* out = (float*)d_out;

    __half *xh, *Wqh, *Wkh, *Wvh, *Woh, *Qh, *Kh, *Vh, *AOh;
    cudaGetSymbolAddress((void**)&xh,  g_xh);
    cudaGetSymbolAddress((void**)&Wqh, g_Wqh);
    cudaGetSymbolAddress((void**)&Wkh, g_Wkh);
    cudaGetSymbolAddress((void**)&Wvh, g_Wvh);
    cudaGetSymbolAddress((void**)&Woh, g_Woh);
    cudaGetSymbolAddress((void**)&Qh,  g_Qh);
    cudaGetSymbolAddress((void**)&Kh,  g_Kh);
    cudaGetSymbolAddress((void**)&Vh,  g_Vh);
    cudaGetSymbolAddress((void**)&AOh, g_AOh);

    cudaFuncSetAttribute(hgemm<2>, cudaFuncAttributeMaxDynamicSharedMemorySize, GEMM_SMEM(2));
    cudaFuncSetAttribute(hgemm<1>, cudaFuncAttributeMaxDynamicSharedMemorySize, GEMM_SMEM(1));
    cudaFuncSetAttribute(flash_h2, cudaFuncAttributeMaxDynamicSharedMemorySize, FLASH_SMEM);

    // fused input conversion + rope table (one launch)
    conv_table<<<NCONV_BLK + NTAB_BLK, 256>>>(x, Wq, Wk, Wv, Wo);

    // fused QKV projection (fp16 out): tiles 0-15 -> Q, 16-19 -> K, 20-23 -> V
    hgemm<2><<<dim3(24, M_ROWS/128), 256, GEMM_SMEM(2)>>>(
        xh, Wqh, Wkh, Wvh, Qh, Kh, Vh, 16, 4, DMODEL, 1);

    // in-place RoPE on K only (Q roped inside flash prologue)
    rope_k_kernel<<<(NK_ROPE + 255)/256, 256>>>(Kh);

    flash_h2<<<dim3(32, HQ, BATCH), 128, FLASH_SMEM>>>(Qh, Kh, Vh, AOh);

    // output projection (fp32 out), 64-row tiles: 1024 CTAs
    hgemm<1><<<dim3(16, M_ROWS/64), 256, GEMM_SMEM(1)>>>(
        AOh, Woh, Woh, Woh, out, out, out, 16, 0, DMODEL, 0);
}